// round 4
// baseline (speedup 1.0000x reference)
#include <cuda_runtime.h>

// Problem constants (fixed by the dataset): B=2048, T=512, K=8, D=8
#define T_DIM 512
#define K_DIM 8
#define D_DIM 8
#define PSTR  192              // floats per (t,k) param slot
#define NPAR  (T_DIM * K_DIM)  // 4096

// Precomputed, duplicated-layout parameters:
// [0..127]   Q[i][j] duplicated (each value stored twice, adjacent)
// [128..143] -mu'_j duplicated   (mu'_j = sum_i c_i Q[i][j])
// [144..159] -0.5/(var_j * ln2) duplicated
// [160..175] 1/sqrt(2*pi*var_j) duplicated
// [176]      softmax weight w_k
__device__ float g_params[NPAR * PSTR];

typedef unsigned long long ull;

__device__ __forceinline__ ull pack2(float lo, float hi) {
    ull r; asm("mov.b64 %0, {%1, %2};" : "=l"(r) : "f"(lo), "f"(hi)); return r;
}
__device__ __forceinline__ void unpack2(ull v, float& lo, float& hi) {
    asm("mov.b64 {%0, %1}, %2;" : "=f"(lo), "=f"(hi) : "l"(v));
}
__device__ __forceinline__ ull fma2(ull a, ull b, ull c) {
    ull d; asm("fma.rn.f32x2 %0, %1, %2, %3;" : "=l"(d) : "l"(a), "l"(b), "l"(c)); return d;
}
__device__ __forceinline__ ull mul2(ull a, ull b) {
    ull d; asm("mul.rn.f32x2 %0, %1, %2;" : "=l"(d) : "l"(a), "l"(b)); return d;
}
__device__ __forceinline__ float ex2f_fast(float x) {
    float r; asm("ex2.approx.ftz.f32 %0, %1;" : "=f"(r) : "f"(x)); return r;
}

// ---------------------------------------------------------------------------
// Precompute kernel: one thread per (t,k) matrix.
//   A antisymmetric from cov_param; Q = (I-A)(I+A)^{-1} via unpivoted
//   Gauss-Jordan (always safe: leading minors of I+A have det >= 1).
//   Folds centers, variance constants and softmax weights.
// ---------------------------------------------------------------------------
__global__ __launch_bounds__(128)
void precompute_k(const float* __restrict__ centers,
                  const float* __restrict__ wl,
                  const float* __restrict__ lv,
                  const float* __restrict__ cov)
{
    int idx = blockIdx.x * 128 + threadIdx.x;   // t*K + k
    if (idx >= NPAR) return;
    int t = idx >> 3;

    const float* v = cov + idx * 28;

    float A[8][8];
#pragma unroll
    for (int i = 0; i < 8; i++)
#pragma unroll
        for (int j = 0; j < 8; j++) A[i][j] = 0.f;

    // a_flat = concat([v, v[::-1], zeros(8)]) reshaped [8,8]; strict-upper mask;
    // A = 0.5*(ut^T - ut)
#pragma unroll
    for (int i = 0; i < 8; i++) {
#pragma unroll
        for (int j = 0; j < 8; j++) {
            if (j > i) {
                int f = i * 8 + j;
                float val = (f < 28) ? v[f] : ((f < 56) ? v[55 - f] : 0.f);
                A[i][j] = -0.5f * val;
                A[j][i] =  0.5f * val;
            }
        }
    }

    // M = I + A ; V = I
    float M[8][8], V[8][8];
#pragma unroll
    for (int i = 0; i < 8; i++)
#pragma unroll
        for (int j = 0; j < 8; j++) {
            M[i][j] = A[i][j] + (i == j ? 1.f : 0.f);
            V[i][j] = (i == j ? 1.f : 0.f);
        }

    // Gauss-Jordan, no pivoting
#pragma unroll
    for (int p = 0; p < 8; p++) {
        float inv = 1.0f / M[p][p];
#pragma unroll
        for (int c = 0; c < 8; c++) { M[p][c] *= inv; V[p][c] *= inv; }
#pragma unroll
        for (int r = 0; r < 8; r++) {
            if (r == p) continue;
            float f = M[r][p];
#pragma unroll
            for (int c = 0; c < 8; c++) {
                M[r][c] = fmaf(-f, M[p][c], M[r][c]);
                V[r][c] = fmaf(-f, V[p][c], V[r][c]);
            }
        }
    }

    // Q = (I - A) * V = M^T * V; using (I-A)[i][m] = delta(i,m) - A[i][m]:
    // Q[i][j] = V[i][j] + sum_m A[m][i] * V[m][j]   (since -A[i][m] = A[m][i])
    float Q[8][8];
#pragma unroll
    for (int i = 0; i < 8; i++) {
#pragma unroll
        for (int j = 0; j < 8; j++) {
            float q = V[i][j];
#pragma unroll
            for (int m = 0; m < 8; m++) q = fmaf(A[m][i], V[m][j], q);
            Q[i][j] = q;
        }
    }

    float* o = g_params + (size_t)idx * PSTR;

    // Q duplicated
#pragma unroll
    for (int i = 0; i < 8; i++)
#pragma unroll
        for (int j = 0; j < 8; j++) {
            o[2 * (i * 8 + j)]     = Q[i][j];
            o[2 * (i * 8 + j) + 1] = Q[i][j];
        }

    // -mu'_j = -(sum_i c_i Q[i][j]), duplicated
    const float* c = centers + idx * 8;
    float cr[8];
#pragma unroll
    for (int i = 0; i < 8; i++) cr[i] = c[i];
#pragma unroll
    for (int j = 0; j < 8; j++) {
        float mu = 0.f;
#pragma unroll
        for (int i = 0; i < 8; i++) mu = fmaf(cr[i], Q[i][j], mu);
        o[128 + 2 * j] = -mu;
        o[129 + 2 * j] = -mu;
    }

    // variance-derived constants
    const float* lvp = lv + idx * 8;
#pragma unroll
    for (int d = 0; d < 8; d++) {
        float l = lvp[d];
        l = fminf(fmaxf(l, -3.5f), 3.5f);
        float var = expf(l);
        float negc2 = -0.72134752f / var;            // -0.5/(var*ln2)
        float nc    = rsqrtf(6.28318530718f * var);  // 1/sqrt(2*pi*var)
        o[144 + 2 * d] = negc2; o[145 + 2 * d] = negc2;
        o[160 + 2 * d] = nc;    o[161 + 2 * d] = nc;
    }

    // softmax over clipped weight logits (per-t, recomputed per thread)
    const float* wrow = wl + t * 8;
    float wc[8], wmax = -1e30f;
#pragma unroll
    for (int k = 0; k < 8; k++) {
        wc[k] = fminf(fmaxf(wrow[k], -3.5f), 3.5f);
        wmax = fmaxf(wmax, wc[k]);
    }
    float wsum = 0.f;
#pragma unroll
    for (int k = 0; k < 8; k++) { wc[k] = expf(wc[k] - wmax); wsum += wc[k]; }
    o[176] = wc[idx & 7] / wsum;
}

// ---------------------------------------------------------------------------
// Main kernel: block = (one t) x (512 batch rows, 2 per thread, packed f32x2).
//   p[b,t] = sum_k w_k * prod_d ( nc_d * 2^( -xt_d^2 * 0.5/(var_d ln2) ) + eps )
//   with xt = x @ Q - mu'   (packed fma.rn.f32x2, Q pre-duplicated in smem)
// ---------------------------------------------------------------------------
__global__ __launch_bounds__(256)
void mix_k(const float* __restrict__ x, float* __restrict__ out)
{
    __shared__ float sp[K_DIM * PSTR];   // 6 KB

    int t = blockIdx.x;
    {
        const float4* g4 = (const float4*)(g_params + (size_t)t * K_DIM * PSTR);
        float4* s4 = (float4*)sp;
        for (int i = threadIdx.x; i < K_DIM * PSTR / 4; i += 256) s4[i] = g4[i];
    }
    __syncthreads();

    int b0 = blockIdx.y * 512 + threadIdx.x;
    int b1 = b0 + 256;

    const float4* xp0 = (const float4*)(x + ((size_t)b0 * T_DIM + t) * D_DIM);
    const float4* xp1 = (const float4*)(x + ((size_t)b1 * T_DIM + t) * D_DIM);
    float4 a0 = xp0[0], a1 = xp0[1];
    float4 c0 = xp1[0], c1 = xp1[1];

    ull xv[8];
    xv[0] = pack2(a0.x, c0.x); xv[1] = pack2(a0.y, c0.y);
    xv[2] = pack2(a0.z, c0.z); xv[3] = pack2(a0.w, c0.w);
    xv[4] = pack2(a1.x, c1.x); xv[5] = pack2(a1.y, c1.y);
    xv[6] = pack2(a1.z, c1.z); xv[7] = pack2(a1.w, c1.w);

    const ull epsp = pack2(1e-7f, 1e-7f);
    float p0 = 0.f, p1 = 0.f;

#pragma unroll 1
    for (int k = 0; k < K_DIM; k++) {
        const float* P = sp + k * PSTR;

        ull acc[8];
#pragma unroll
        for (int j = 0; j < 8; j++)
            acc[j] = *(const ull*)(P + 128 + 2 * j);   // init with -mu' (packed)

#pragma unroll
        for (int i = 0; i < 8; i++) {
            const ull* qrow = (const ull*)(P + 16 * i);
#pragma unroll
            for (int j = 0; j < 8; j++)
                acc[j] = fma2(xv[i], qrow[j], acc[j]);
        }

        ull pk = pack2(1.f, 1.f);
#pragma unroll
        for (int j = 0; j < 8; j++) {
            ull z = mul2(acc[j], acc[j]);                       // xt^2
            ull m = mul2(z, *(const ull*)(P + 144 + 2 * j));    // * -0.5/(var ln2)
            float m0, m1; unpack2(m, m0, m1);
            ull e = pack2(ex2f_fast(m0), ex2f_fast(m1));        // exp(-0.5 xt^2/var)
            ull term = fma2(*(const ull*)(P + 160 + 2 * j), e, epsp);  // nc*e + eps
            pk = mul2(pk, term);
        }

        float q0, q1; unpack2(pk, q0, q1);
        float w = P[176];
        p0 = fmaf(w, q0, p0);
        p1 = fmaf(w, q1, p1);
    }

    out[(size_t)b0 * T_DIM + t] = p0;
    out[(size_t)b1 * T_DIM + t] = p1;
}

// ---------------------------------------------------------------------------
// Inputs (metadata order): x[B,T,D], kernel_centers[T,K,D], weight_logits[T,K],
//                          log_variance[T,K,D], cov_param[T,K,28]
// Output: p[B,T] float32
// ---------------------------------------------------------------------------
extern "C" void kernel_launch(void* const* d_in, const int* in_sizes, int n_in,
                              void* d_out, int out_size)
{
    const float* x       = (const float*)d_in[0];
    const float* centers = (const float*)d_in[1];
    const float* wl      = (const float*)d_in[2];
    const float* lv      = (const float*)d_in[3];
    const float* cov     = (const float*)d_in[4];

    int B = in_sizes[0] / (T_DIM * D_DIM);   // 2048

    precompute_k<<<(NPAR + 127) / 128, 128>>>(centers, wl, lv, cov);

    dim3 grid(T_DIM, B / 512);
    mix_k<<<grid, 256>>>(x, (float*)d_out);
}

// round 6
// speedup vs baseline: 1.2859x; 1.2859x over previous
#include <cuda_runtime.h>

// Problem constants (fixed by the dataset): B=2048, T=512, K=8, D=8
#define T_DIM 512
#define K_DIM 8
#define D_DIM 8
#define PSTR  192              // floats per (t,k) param slot
#define NPAR  (T_DIM * K_DIM)  // 4096

// Precomputed, duplicated-layout parameters per (t,k):
// [0..127]   Q[i][j] duplicated (value stored twice, adjacent) at 2*(i*8+j)
// [128..143] -mu'_j duplicated   (mu'_j = sum_i c_i Q[i][j])
// [144..159] -0.5/(var_j * ln2) duplicated
// [160..175] 1/sqrt(2*pi*var_j) duplicated
// [176]      softmax weight w_k
__device__ float g_params[NPAR * PSTR];

typedef unsigned long long ull;

__device__ __forceinline__ ull pack2(float lo, float hi) {
    ull r; asm("mov.b64 %0, {%1, %2};" : "=l"(r) : "f"(lo), "f"(hi)); return r;
}
__device__ __forceinline__ void unpack2(ull v, float& lo, float& hi) {
    asm("mov.b64 {%0, %1}, %2;" : "=f"(lo), "=f"(hi) : "l"(v));
}
__device__ __forceinline__ ull fma2(ull a, ull b, ull c) {
    ull d; asm("fma.rn.f32x2 %0, %1, %2, %3;" : "=l"(d) : "l"(a), "l"(b), "l"(c)); return d;
}
__device__ __forceinline__ ull mul2(ull a, ull b) {
    ull d; asm("mul.rn.f32x2 %0, %1, %2;" : "=l"(d) : "l"(a), "l"(b)); return d;
}
__device__ __forceinline__ float ex2f_fast(float x) {
    float r; asm("ex2.approx.ftz.f32 %0, %1;" : "=f"(r) : "f"(x)); return r;
}

// ---------------------------------------------------------------------------
// Precompute kernel: one thread per (t,k) matrix.
//   Key identity: Q = (I-A)(I+A)^{-1} = 2*(I+A)^{-1} - I.
//   Only M = I+A and V = M^{-1} live (128 floats) -> no register spills.
//   Unpivoted Gauss-Jordan is safe: leading minors of I+A have det >= 1.
// ---------------------------------------------------------------------------
__global__ __launch_bounds__(128)
void precompute_k(const float* __restrict__ centers,
                  const float* __restrict__ wl,
                  const float* __restrict__ lv,
                  const float* __restrict__ cov)
{
    int idx = blockIdx.x * 128 + threadIdx.x;   // t*K + k
    if (idx >= NPAR) return;
    int t = idx >> 3;

    const float* v = cov + idx * 28;

    // M = I + A, where A = 0.5*(ut^T - ut) and ut is the strict-upper matrix
    // from a_flat = concat([v, v[::-1], zeros(8)]) reshaped [8,8].
    float M[8][8];
#pragma unroll
    for (int i = 0; i < 8; i++) M[i][i] = 1.f;
#pragma unroll
    for (int i = 0; i < 8; i++) {
#pragma unroll
        for (int j = i + 1; j < 8; j++) {
            int f = i * 8 + j;
            float val = (f < 28) ? v[f] : ((f < 56) ? v[55 - f] : 0.f);
            M[i][j] = -0.5f * val;
            M[j][i] =  0.5f * val;
        }
    }

    // V = I; Gauss-Jordan invert M into V (no pivoting needed)
    float V[8][8];
#pragma unroll
    for (int i = 0; i < 8; i++)
#pragma unroll
        for (int j = 0; j < 8; j++) V[i][j] = (i == j) ? 1.f : 0.f;

#pragma unroll
    for (int p = 0; p < 8; p++) {
        float inv = 1.0f / M[p][p];
#pragma unroll
        for (int c = 0; c < 8; c++) { M[p][c] *= inv; V[p][c] *= inv; }
#pragma unroll
        for (int r = 0; r < 8; r++) {
            if (r == p) continue;
            float f = M[r][p];
#pragma unroll
            for (int c = 0; c < 8; c++) {
                M[r][c] = fmaf(-f, M[p][c], M[r][c]);
                V[r][c] = fmaf(-f, V[p][c], V[r][c]);
            }
        }
    }

    float* o = g_params + (size_t)idx * PSTR;
    const float* c = centers + idx * 8;

    // Q = 2V - I ; write duplicated and fold mu' = c @ Q in the same pass
    float mu[8];
#pragma unroll
    for (int j = 0; j < 8; j++) mu[j] = 0.f;
#pragma unroll
    for (int i = 0; i < 8; i++) {
        float ci = c[i];
#pragma unroll
        for (int j = 0; j < 8; j++) {
            float q = 2.f * V[i][j] - (i == j ? 1.f : 0.f);
            o[2 * (i * 8 + j)]     = q;
            o[2 * (i * 8 + j) + 1] = q;
            mu[j] = fmaf(ci, q, mu[j]);
        }
    }
#pragma unroll
    for (int j = 0; j < 8; j++) { o[128 + 2 * j] = -mu[j]; o[129 + 2 * j] = -mu[j]; }

    // variance-derived constants
    const float* lvp = lv + idx * 8;
#pragma unroll
    for (int d = 0; d < 8; d++) {
        float l = lvp[d];
        l = fminf(fmaxf(l, -3.5f), 3.5f);
        float var = expf(l);
        float negc2 = -0.72134752f / var;            // -0.5/(var*ln2)
        float nc    = rsqrtf(6.28318530718f * var);  // 1/sqrt(2*pi*var)
        o[144 + 2 * d] = negc2; o[145 + 2 * d] = negc2;
        o[160 + 2 * d] = nc;    o[161 + 2 * d] = nc;
    }

    // softmax over clipped weight logits (per-t, recomputed per thread)
    const float* wrow = wl + t * 8;
    float wc[8], wmax = -1e30f;
#pragma unroll
    for (int k = 0; k < 8; k++) {
        wc[k] = fminf(fmaxf(wrow[k], -3.5f), 3.5f);
        wmax = fmaxf(wmax, wc[k]);
    }
    float wsum = 0.f;
#pragma unroll
    for (int k = 0; k < 8; k++) { wc[k] = expf(wc[k] - wmax); wsum += wc[k]; }
    o[176] = wc[idx & 7] / wsum;
}

// ---------------------------------------------------------------------------
// Main kernel: block = one t x 128 threads, 8 batch rows per thread
// (4 packed f32x2 pairs). j-outer matvec so only one acc column is live per
// pair -> each smem param load feeds 4 fma2's (4x less LDS than R3 kernel).
//   p[b,t] = sum_k w_k * prod_d ( nc_d * 2^( -xt_d^2 * 0.5/(var_d ln2) ) + eps )
// ---------------------------------------------------------------------------
__global__ __launch_bounds__(128)
void mix_k(const float* __restrict__ x, float* __restrict__ out)
{
    __shared__ float sp[K_DIM * PSTR];   // 6 KB

    int t = blockIdx.x;
    {
        const float4* g4 = (const float4*)(g_params + (size_t)t * K_DIM * PSTR);
        float4* s4 = (float4*)sp;
#pragma unroll
        for (int i = 0; i < 3; i++)
            s4[threadIdx.x + i * 128] = g4[threadIdx.x + i * 128];
    }
    __syncthreads();

    int bbase = blockIdx.y * 1024 + threadIdx.x;

    // Load 8 batch rows (4 pairs), pack into f32x2 registers
    ull xv[4][8];
#pragma unroll
    for (int pr = 0; pr < 4; pr++) {
        int bA = bbase + pr * 256;
        int bB = bA + 128;
        const float4* xpA = (const float4*)(x + ((size_t)bA * T_DIM + t) * D_DIM);
        const float4* xpB = (const float4*)(x + ((size_t)bB * T_DIM + t) * D_DIM);
        float4 a0 = xpA[0], a1 = xpA[1];
        float4 c0 = xpB[0], c1 = xpB[1];
        xv[pr][0] = pack2(a0.x, c0.x); xv[pr][1] = pack2(a0.y, c0.y);
        xv[pr][2] = pack2(a0.z, c0.z); xv[pr][3] = pack2(a0.w, c0.w);
        xv[pr][4] = pack2(a1.x, c1.x); xv[pr][5] = pack2(a1.y, c1.y);
        xv[pr][6] = pack2(a1.z, c1.z); xv[pr][7] = pack2(a1.w, c1.w);
    }

    const ull epsp = pack2(1e-7f, 1e-7f);
    float p[8];
#pragma unroll
    for (int i = 0; i < 8; i++) p[i] = 0.f;

#pragma unroll 1
    for (int k = 0; k < K_DIM; k++) {
        const float* P = sp + k * PSTR;

        ull pk[4];
#pragma unroll
        for (int pr = 0; pr < 4; pr++) pk[pr] = pack2(1.f, 1.f);

#pragma unroll
        for (int j = 0; j < 8; j++) {
            ull mu = *(const ull*)(P + 128 + 2 * j);
            ull acc[4];
#pragma unroll
            for (int pr = 0; pr < 4; pr++) acc[pr] = mu;

#pragma unroll
            for (int i = 0; i < 8; i++) {
                ull qv = *(const ull*)(P + 16 * i + 2 * j);   // Q[i][j] duplicated
#pragma unroll
                for (int pr = 0; pr < 4; pr++)
                    acc[pr] = fma2(xv[pr][i], qv, acc[pr]);
            }

            ull c2 = *(const ull*)(P + 144 + 2 * j);
            ull nc = *(const ull*)(P + 160 + 2 * j);
#pragma unroll
            for (int pr = 0; pr < 4; pr++) {
                ull z = mul2(acc[pr], acc[pr]);               // xt^2
                ull m = mul2(z, c2);                          // * -0.5/(var ln2)
                float m0, m1; unpack2(m, m0, m1);
                ull e = pack2(ex2f_fast(m0), ex2f_fast(m1));  // exp(-0.5 xt^2/var)
                ull term = fma2(nc, e, epsp);                 // nc*e + eps
                pk[pr] = mul2(pk[pr], term);
            }
        }

        float w = P[176];
#pragma unroll
        for (int pr = 0; pr < 4; pr++) {
            float q0, q1; unpack2(pk[pr], q0, q1);
            p[2 * pr]     = fmaf(w, q0, p[2 * pr]);
            p[2 * pr + 1] = fmaf(w, q1, p[2 * pr + 1]);
        }
    }

#pragma unroll
    for (int pr = 0; pr < 4; pr++) {
        int bA = bbase + pr * 256;
        int bB = bA + 128;
        out[(size_t)bA * T_DIM + t] = p[2 * pr];
        out[(size_t)bB * T_DIM + t] = p[2 * pr + 1];
    }
}

// ---------------------------------------------------------------------------
// Inputs (metadata order): x[B,T,D], kernel_centers[T,K,D], weight_logits[T,K],
//                          log_variance[T,K,D], cov_param[T,K,28]
// Output: p[B,T] float32
// ---------------------------------------------------------------------------
extern "C" void kernel_launch(void* const* d_in, const int* in_sizes, int n_in,
                              void* d_out, int out_size)
{
    const float* x       = (const float*)d_in[0];
    const float* centers = (const float*)d_in[1];
    const float* wl      = (const float*)d_in[2];
    const float* lv      = (const float*)d_in[3];
    const float* cov     = (const float*)d_in[4];

    int B = in_sizes[0] / (T_DIM * D_DIM);   // 2048

    precompute_k<<<(NPAR + 127) / 128, 128>>>(centers, wl, lv, cov);

    dim3 grid(T_DIM, B / 1024);
    mix_k<<<grid, 128>>>(x, (float*)d_out);
}

// round 9
// speedup vs baseline: 1.8588x; 1.4456x over previous
#include <cuda_runtime.h>

// Problem constants (fixed by the dataset): B=2048, T=512, K=8, D=8
#define T_DIM 512
#define K_DIM 8
#define D_DIM 8
#define PSTR  192              // floats per (t,k) param slot
#define NPAR  (T_DIM * K_DIM)  // 4096

// Precomputed, duplicated-layout parameters per (t,k):
// [0..127]   Q[i][j] duplicated (value stored twice, adjacent) at 2*(i*8+j)
// [128..143] -mu'_j duplicated   (mu'_j = sum_i c_i Q[i][j])
// [144..159] -0.5/(var_j * ln2) duplicated
// [160..175] 1/sqrt(2*pi*var_j) duplicated
// [176]      softmax weight w_k
__device__ float g_params[NPAR * PSTR];

typedef unsigned long long ull;

__device__ __forceinline__ ull pack2(float lo, float hi) {
    ull r; asm("mov.b64 %0, {%1, %2};" : "=l"(r) : "f"(lo), "f"(hi)); return r;
}
__device__ __forceinline__ void unpack2(ull v, float& lo, float& hi) {
    asm("mov.b64 {%0, %1}, %2;" : "=f"(lo), "=f"(hi) : "l"(v));
}
__device__ __forceinline__ ull fma2(ull a, ull b, ull c) {
    ull d; asm("fma.rn.f32x2 %0, %1, %2, %3;" : "=l"(d) : "l"(a), "l"(b), "l"(c)); return d;
}
__device__ __forceinline__ ull mul2(ull a, ull b) {
    ull d; asm("mul.rn.f32x2 %0, %1, %2;" : "=l"(d) : "l"(a), "l"(b)); return d;
}
__device__ __forceinline__ float ex2f_fast(float x) {
    float r; asm("ex2.approx.ftz.f32 %0, %1;" : "=f"(r) : "f"(x)); return r;
}

// ---------------------------------------------------------------------------
// Precompute kernel v2: 8 threads per (t,k) matrix (one per row).
//   Row-parallel unpivoted Gauss-Jordan; pivot rows broadcast with
//   __shfl_sync(width=8). Q = (I-A)(I+A)^{-1} = 2*(I+A)^{-1} - I.
//   32768 threads total -> full-chip, short dependency chains, no spills.
// ---------------------------------------------------------------------------
__global__ __launch_bounds__(256)
void precompute_k(const float* __restrict__ centers,
                  const float* __restrict__ wl,
                  const float* __restrict__ lv,
                  const float* __restrict__ cov)
{
    int gtid = blockIdx.x * 256 + threadIdx.x;   // exactly NPAR*8 threads
    int idx  = gtid >> 3;        // matrix index = t*K + k
    int r    = gtid & 7;         // row owned by this thread
    int t    = idx >> 3;
    int kk   = idx & 7;

    const unsigned FULL = 0xffffffffu;
    const float* v = cov + idx * 28;

    // Row r of M = I + A, where A = 0.5*(ut^T - ut), ut from
    // a_flat = concat([v, v[::-1], zeros(8)]) reshaped [8,8], strict upper.
    float Mr[8], Vr[8];
#pragma unroll
    for (int c = 0; c < 8; c++) {
        if (c == r) {
            Mr[c] = 1.f;
        } else {
            int i = (r < c) ? r : c;
            int j = (r < c) ? c : r;
            int f = i * 8 + j;                       // 1..55
            float val = (f < 28) ? v[f] : v[55 - f];
            Mr[c] = (r < c) ? (-0.5f * val) : (0.5f * val);
        }
        Vr[c] = (c == r) ? 1.f : 0.f;
    }

    // Row-parallel Gauss-Jordan (no pivoting: I+A leading minors det >= 1)
#pragma unroll
    for (int p = 0; p < 8; p++) {
        float Mp[8], Vp[8];
#pragma unroll
        for (int c = 0; c < 8; c++) {
            Mp[c] = __shfl_sync(FULL, Mr[c], p, 8);
            Vp[c] = __shfl_sync(FULL, Vr[c], p, 8);
        }
        float inv = 1.0f / Mp[p];
        if (r == p) {
#pragma unroll
            for (int c = 0; c < 8; c++) { Mr[c] = Mp[c] * inv; Vr[c] = Vp[c] * inv; }
        } else {
            float f2 = Mr[p] * inv;
#pragma unroll
            for (int c = 0; c < 8; c++) {
                Mr[c] = fmaf(-f2, Mp[c], Mr[c]);
                Vr[c] = fmaf(-f2, Vp[c], Vr[c]);
            }
        }
    }

    float* o = g_params + (size_t)idx * PSTR;

    // Q row r = 2*Vr - e_r ; write duplicated, accumulate mu partials
    float cr = centers[idx * 8 + r];
    float Qr[8], mu[8];
#pragma unroll
    for (int j = 0; j < 8; j++) {
        Qr[j] = 2.f * Vr[j] - (j == r ? 1.f : 0.f);
        o[2 * (r * 8 + j)]     = Qr[j];
        o[2 * (r * 8 + j) + 1] = Qr[j];
        mu[j] = cr * Qr[j];
    }
    // 8-lane butterfly reduce: mu_j = sum_i c_i Q[i][j]
#pragma unroll
    for (int off = 4; off >= 1; off >>= 1) {
#pragma unroll
        for (int j = 0; j < 8; j++)
            mu[j] += __shfl_xor_sync(FULL, mu[j], off, 8);
    }
    o[128 + 2 * r] = -mu[r];
    o[129 + 2 * r] = -mu[r];

    // variance-derived constants, one dim per lane
    {
        float l = lv[idx * 8 + r];
        l = fminf(fmaxf(l, -3.5f), 3.5f);
        float var = expf(l);
        float negc2 = -0.72134752f / var;            // -0.5/(var*ln2)
        float nc    = rsqrtf(6.28318530718f * var);  // 1/sqrt(2*pi*var)
        o[144 + 2 * r] = negc2; o[145 + 2 * r] = negc2;
        o[160 + 2 * r] = nc;    o[161 + 2 * r] = nc;
    }

    // softmax over clipped weight logits for row t; pick component kk
    {
        float wc = fminf(fmaxf(wl[t * 8 + r], -3.5f), 3.5f);
        float m = wc;
#pragma unroll
        for (int off = 4; off >= 1; off >>= 1)
            m = fmaxf(m, __shfl_xor_sync(FULL, m, off, 8));
        float e = expf(wc - m);
        float s = e;
#pragma unroll
        for (int off = 4; off >= 1; off >>= 1)
            s += __shfl_xor_sync(FULL, s, off, 8);
        float esel = __shfl_sync(FULL, e, kk, 8);
        if (r == 0) o[176] = esel / s;
    }
}

// ---------------------------------------------------------------------------
// Main kernel: block = one t x 128 threads, 8 batch rows per thread
// (4 packed f32x2 pairs). j-outer matvec so each smem param load feeds
// 4 fma2's.
//   p[b,t] = sum_k w_k * prod_d ( nc_d * 2^( -xt_d^2 * 0.5/(var_d ln2) ) + eps )
// ---------------------------------------------------------------------------
__global__ __launch_bounds__(128)
void mix_k(const float* __restrict__ x, float* __restrict__ out)
{
    __shared__ float sp[K_DIM * PSTR];   // 6 KB

    int t = blockIdx.x;
    {
        const float4* g4 = (const float4*)(g_params + (size_t)t * K_DIM * PSTR);
        float4* s4 = (float4*)sp;
#pragma unroll
        for (int i = 0; i < 3; i++)
            s4[threadIdx.x + i * 128] = g4[threadIdx.x + i * 128];
    }
    __syncthreads();

    int bbase = blockIdx.y * 1024 + threadIdx.x;

    // Load 8 batch rows (4 pairs), pack into f32x2 registers
    ull xv[4][8];
#pragma unroll
    for (int pr = 0; pr < 4; pr++) {
        int bA = bbase + pr * 256;
        int bB = bA + 128;
        const float4* xpA = (const float4*)(x + ((size_t)bA * T_DIM + t) * D_DIM);
        const float4* xpB = (const float4*)(x + ((size_t)bB * T_DIM + t) * D_DIM);
        float4 a0 = xpA[0], a1 = xpA[1];
        float4 c0 = xpB[0], c1 = xpB[1];
        xv[pr][0] = pack2(a0.x, c0.x); xv[pr][1] = pack2(a0.y, c0.y);
        xv[pr][2] = pack2(a0.z, c0.z); xv[pr][3] = pack2(a0.w, c0.w);
        xv[pr][4] = pack2(a1.x, c1.x); xv[pr][5] = pack2(a1.y, c1.y);
        xv[pr][6] = pack2(a1.z, c1.z); xv[pr][7] = pack2(a1.w, c1.w);
    }

    const ull epsp = pack2(1e-7f, 1e-7f);
    float p[8];
#pragma unroll
    for (int i = 0; i < 8; i++) p[i] = 0.f;

#pragma unroll 1
    for (int k = 0; k < K_DIM; k++) {
        const float* P = sp + k * PSTR;

        ull pk[4];
#pragma unroll
        for (int pr = 0; pr < 4; pr++) pk[pr] = pack2(1.f, 1.f);

#pragma unroll
        for (int j = 0; j < 8; j++) {
            ull mu = *(const ull*)(P + 128 + 2 * j);
            ull acc[4];
#pragma unroll
            for (int pr = 0; pr < 4; pr++) acc[pr] = mu;

#pragma unroll
            for (int i = 0; i < 8; i++) {
                ull qv = *(const ull*)(P + 16 * i + 2 * j);   // Q[i][j] duplicated
#pragma unroll
                for (int pr = 0; pr < 4; pr++)
                    acc[pr] = fma2(xv[pr][i], qv, acc[pr]);
            }

            ull c2 = *(const ull*)(P + 144 + 2 * j);
            ull nc = *(const ull*)(P + 160 + 2 * j);
#pragma unroll
            for (int pr = 0; pr < 4; pr++) {
                ull z = mul2(acc[pr], acc[pr]);               // xt^2
                ull m = mul2(z, c2);                          // * -0.5/(var ln2)
                float m0, m1; unpack2(m, m0, m1);
                ull e = pack2(ex2f_fast(m0), ex2f_fast(m1));  // exp(-0.5 xt^2/var)
                ull term = fma2(nc, e, epsp);                 // nc*e + eps
                pk[pr] = mul2(pk[pr], term);
            }
        }

        float w = P[176];
#pragma unroll
        for (int pr = 0; pr < 4; pr++) {
            float q0, q1; unpack2(pk[pr], q0, q1);
            p[2 * pr]     = fmaf(w, q0, p[2 * pr]);
            p[2 * pr + 1] = fmaf(w, q1, p[2 * pr + 1]);
        }
    }

#pragma unroll
    for (int pr = 0; pr < 4; pr++) {
        int bA = bbase + pr * 256;
        int bB = bA + 128;
        out[(size_t)bA * T_DIM + t] = p[2 * pr];
        out[(size_t)bB * T_DIM + t] = p[2 * pr + 1];
    }
}

// ---------------------------------------------------------------------------
// Inputs (metadata order): x[B,T,D], kernel_centers[T,K,D], weight_logits[T,K],
//                          log_variance[T,K,D], cov_param[T,K,28]
// Output: p[B,T] float32
// ---------------------------------------------------------------------------
extern "C" void kernel_launch(void* const* d_in, const int* in_sizes, int n_in,
                              void* d_out, int out_size)
{
    const float* x       = (const float*)d_in[0];
    const float* centers = (const float*)d_in[1];
    const float* wl      = (const float*)d_in[2];
    const float* lv      = (const float*)d_in[3];
    const float* cov     = (const float*)d_in[4];

    int B = in_sizes[0] / (T_DIM * D_DIM);   // 2048

    precompute_k<<<(NPAR * 8) / 256, 256>>>(centers, wl, lv, cov);

    dim3 grid(T_DIM, B / 1024);
    mix_k<<<grid, 128>>>(x, (float*)d_out);
}